// round 15
// baseline (speedup 1.0000x reference)
#include <cuda_runtime.h>

#define C   512
#define T   8192
#define TN  8176      // T - WINDOW
#define PAD 8         // WINDOW/2 == RADIUS
#define NX  8208      // padded length T + 16

// Scratch (device globals: no allocation allowed in kernel_launch)
__device__ float g_Sct[(size_t)C * TN];   // window sums, [c][t]  (t minor)
__device__ float g_K  [(size_t)TN * C];   // kurtosis,    [t][c]  (c minor)

// ---------------------------------------------------------------------------
// K1: cumsum = XLA ReduceWindowRewriter(base=16) blocked scan, THREE blocked
// levels (VERIFIED: sequential level-3 regressed 2 -> 85 flips). FROZEN.
// ---------------------------------------------------------------------------
__global__ void k_cumsum(const float* __restrict__ inp) {
    __shared__ float xs[NX];
    __shared__ float t1[513];
    __shared__ float in2[513];
    __shared__ float t2[33];
    __shared__ float in3[33];
    __shared__ float t3[3];
    __shared__ float o3[3];
    __shared__ float s33[33];
    __shared__ float s513[513];

    const int c   = blockIdx.x;
    const int tid = threadIdx.x;   // 128
    const float* row = inp + (size_t)c * T;

    for (int j = tid; j < NX; j += 128)
        xs[j] = (j >= 8 && j < 8200) ? row[j - 8] : 0.0f;
    __syncthreads();

    for (int b = tid; b < 513; b += 128) {
        float acc = 0.0f;
        const int base = b * 16;
#pragma unroll
        for (int j = 0; j < 16; j++) {
            acc = __fadd_rn(acc, xs[base + j]);
            xs[base + j] = acc;
        }
        t1[b] = acc;
    }
    __syncthreads();

    if (tid < 33) {
        float acc = 0.0f;
        const int base = tid * 16;
#pragma unroll
        for (int j = 0; j < 16; j++) {
            const int i = base + j;
            const float v = (i < 513) ? t1[i] : 0.0f;
            acc = __fadd_rn(acc, v);
            if (i < 513) in2[i] = acc;
        }
        t2[tid] = acc;
    }
    __syncthreads();

    if (tid < 3) {
        float acc = 0.0f;
        const int base = tid * 16;
#pragma unroll
        for (int j = 0; j < 16; j++) {
            const int i = base + j;
            const float v = (i < 33) ? t2[i] : 0.0f;
            acc = __fadd_rn(acc, v);
            if (i < 33) in3[i] = acc;
        }
        t3[tid] = acc;
    }
    __syncthreads();

    if (tid == 0) {
        float a = t3[0];             o3[0] = a;
        a = __fadd_rn(a, t3[1]);     o3[1] = a;
        a = __fadd_rn(a, t3[2]);     o3[2] = a;
    }
    __syncthreads();

    if (tid < 33) {
        const int p = tid;
        const float v = in3[p];
        s33[p] = (p >= 16) ? __fadd_rn(o3[(p >> 4) - 1], v) : v;
    }
    __syncthreads();

    for (int m = tid; m < 513; m += 128) {
        const float v = in2[m];
        s513[m] = (m >= 16) ? __fadd_rn(s33[(m >> 4) - 1], v) : v;
    }
    __syncthreads();

    float* srow = g_Sct + (size_t)c * TN;
    for (int t = tid; t < TN; t += 128) {
        const int i1 = t + 15;
        float hi = (i1 >= 16) ? __fadd_rn(s513[(i1 >> 4) - 1], xs[i1]) : xs[i1];
        float lo = 0.0f;
        if (t > 0) {
            const int i0 = t - 1;
            lo = (i0 >= 16) ? __fadd_rn(s513[(i0 >> 4) - 1], xs[i0]) : xs[i0];
        }
        srow[t] = __fadd_rn(hi, -lo);
    }
}

// ---------------------------------------------------------------------------
// K2: kurtosis. THIS ROUND: the UNTESTED quadrant (m2 FUSED, m4 UNFUSED):
//   m2 = fma(d, d, m2)                      (contracted; d*d not pre-rounded)
//   d4 = rn(rn(rn(d*d)*d)*d); m4 = fadd(m4, d4)   (fully rounded chain+acc)
// Quadrant map: (F,F)=R4, (U,F)=R5, (U,U)=R9, (U,Usq)=R13 all -> 2 flips;
// (F,U) untested and uniquely consistent with the flip-distance ledger.
// ---------------------------------------------------------------------------
__global__ void k_kurt() {
    const int t0  = blockIdx.x * 8;
    const int tid = threadIdx.x;            // 512
    __shared__ float sh[8][C + 17];

#pragma unroll
    for (int r = 0; r < 8; r++) {
        int e  = r * 512 + tid;
        int cc = e >> 3, tt = e & 7;
        sh[tt][cc + 8] = g_Sct[(size_t)cc * TN + t0 + tt];
    }
    if (tid < 64) {
        int tt = tid >> 3, j = tid & 7;
        sh[tt][j]         = 0.0f;
        sh[tt][C + 8 + j] = 0.0f;
    }
    __syncthreads();

    const int c = tid;
#pragma unroll
    for (int tt = 0; tt < 8; tt++) {
        float v[17];
#pragma unroll
        for (int i = 0; i < 17; i++) v[i] = sh[tt][c + i];

        float s = 0.0f;
#pragma unroll
        for (int i = 0; i < 17; i++) s = __fadd_rn(s, v[i]);
        float mu = __fdiv_rn(s, 17.0f);

        float m2 = 0.0f, m4 = 0.0f;
#pragma unroll
        for (int i = 0; i < 17; i++) {
            float d  = __fadd_rn(v[i], -mu);
            m2 = __fmaf_rn(d, d, m2);            // FUSED accumulate
            float d2 = __fmul_rn(d, d);          // rounded (for m4 chain)
            float d3 = __fmul_rn(d2, d);
            float d4 = __fmul_rn(d3, d);
            m4 = __fadd_rn(m4, d4);              // UNFUSED accumulate
        }
        m2 = __fdiv_rn(m2, 17.0f);
        m4 = __fdiv_rn(m4, 17.0f);
        float kk = __fadd_rn(__fdiv_rn(m4, __fmul_rn(m2, m2)), -3.0f);

        g_K[(size_t)(t0 + tt) * C + c] = kk;
    }
}

// ---------------------------------------------------------------------------
// K3: serial LIF scan. FROZEN: mem FUSED-LHS (unfused proven +2 flips;
// LHS/RHS both at 2).
// ---------------------------------------------------------------------------
__global__ void k_scan(const float* __restrict__ inp,
                       const float* __restrict__ w_init,
                       float* __restrict__ out) {
    const int c = blockIdx.x * 32 + threadIdx.x;
    const float* xrow = inp + (size_t)c * T;
    float*       orow = out + (size_t)c * T;

    float w   = w_init[c];
    float mem = 0.0f;

    const int D = 16;
    float kb[D], xb[D], kb2[D], xb2[D];

#pragma unroll
    for (int u = 0; u < D; u++) {
        kb[u] = g_K[(size_t)u * C + c];
        xb[u] = (u >= PAD) ? xrow[u - PAD] : 0.0f;
    }

    for (int base = 0; base < TN; base += D) {
        const int nb = base + D;
#pragma unroll
        for (int u = 0; u < D; u++) {
            int t = nb + u;
            kb2[u] = (t < TN) ? g_K[(size_t)t * C + c] : 0.0f;
            xb2[u] = (t < TN) ? xrow[t - PAD] : 0.0f;
        }
#pragma unroll
        for (int u = 0; u < D; u++) {
            float hk = __fmul_rn(0.5f, kb[u]);           // exact
            w = __fmaf_rn(0.5f, w, hk);                  // == rn(0.5w + 0.5k)
            w = fmaxf(w, 0.0f);
            w = fminf(w, 10.0f);

            float wx   = __fmul_rn(w, xb[u]);
            float mem1 = __fmaf_rn(0.95f, mem, wx);      // fused LHS mul
            float d    = __fadd_rn(mem1, -1.0f);
            bool  p    = (d > 0.0f);
            orow[base + u] = p ? 1.0f : 0.0f;
            mem = p ? d : mem1;                          // mem - spk (exact)
        }
#pragma unroll
        for (int u = 0; u < D; u++) { kb[u] = kb2[u]; xb[u] = xb2[u]; }
    }

#pragma unroll
    for (int t = TN; t < T; t++) orow[t] = xrow[t];
}

// ---------------------------------------------------------------------------
extern "C" void kernel_launch(void* const* d_in, const int* in_sizes, int n_in,
                              void* d_out, int out_size) {
    const float* inp    = (const float*)d_in[0];   // (512, 8192) f32
    const float* w_init = (const float*)d_in[1];   // (512,)      f32
    float*       out    = (float*)d_out;           // (512, 8192) f32

    k_cumsum<<<C, 128>>>(inp);
    k_kurt  <<<TN / 8, C>>>();
    k_scan  <<<C / 32, 32>>>(inp, w_init, out);
}

// round 16
// speedup vs baseline: 1.5575x; 1.5575x over previous
#include <cuda_runtime.h>

#define C   512
#define T   8192
#define TN  8176      // T - WINDOW
#define PAD 8         // WINDOW/2 == RADIUS
#define NX  8208      // padded length T + 16

// Scratch (device globals: no allocation allowed in kernel_launch)
__device__ float g_Sct[(size_t)C * TN];   // window sums, [c][t]  (t minor)
__device__ float g_Kct[(size_t)C * TN];   // kurtosis,    [c][t]  (t minor)

// ---------------------------------------------------------------------------
// K1: cumsum = XLA ReduceWindowRewriter(base=16) blocked scan. FP op order
// FROZEN (verified rel_err = 0). This round: register-prefetch the 16-elem
// blocks so the 29-cyc LDS latency is off the serial add chain; 256 threads.
// ---------------------------------------------------------------------------
__global__ void __launch_bounds__(256) k_cumsum(const float* __restrict__ inp) {
    __shared__ float xs[NX];
    __shared__ float t1[513];
    __shared__ float in2[513];
    __shared__ float t2[33];
    __shared__ float in3[33];
    __shared__ float t3[3];
    __shared__ float o3[3];
    __shared__ float s33[33];
    __shared__ float s513[513];

    const int c   = blockIdx.x;
    const int tid = threadIdx.x;   // 256
    const float* row = inp + (size_t)c * T;

    for (int j = tid; j < NX; j += 256)
        xs[j] = (j >= 8 && j < 8200) ? row[j - 8] : 0.0f;
    __syncthreads();

    // Level 1: 513 blocks of 16 — prefetch block to regs, then serial adds
    for (int b = tid; b < 513; b += 256) {
        const int base = b * 16;
        float r[16];
#pragma unroll
        for (int j = 0; j < 16; j++) r[j] = xs[base + j];
        float acc = 0.0f;
#pragma unroll
        for (int j = 0; j < 16; j++) {
            acc = __fadd_rn(acc, r[j]);
            xs[base + j] = acc;
        }
        t1[b] = acc;
    }
    __syncthreads();

    // Level 2: 513 -> 33 blocks of 16 (pad-high with init=0)
    if (tid < 33) {
        float acc = 0.0f;
        const int base = tid * 16;
#pragma unroll
        for (int j = 0; j < 16; j++) {
            const int i = base + j;
            const float v = (i < 513) ? t1[i] : 0.0f;
            acc = __fadd_rn(acc, v);
            if (i < 513) in2[i] = acc;
        }
        t2[tid] = acc;
    }
    __syncthreads();

    // Level 3: 33 -> 3 blocks of 16
    if (tid < 3) {
        float acc = 0.0f;
        const int base = tid * 16;
#pragma unroll
        for (int j = 0; j < 16; j++) {
            const int i = base + j;
            const float v = (i < 33) ? t2[i] : 0.0f;
            acc = __fadd_rn(acc, v);
            if (i < 33) in3[i] = acc;
        }
        t3[tid] = acc;
    }
    __syncthreads();

    if (tid == 0) {
        float a = t3[0];             o3[0] = a;
        a = __fadd_rn(a, t3[1]);     o3[1] = a;
        a = __fadd_rn(a, t3[2]);     o3[2] = a;
    }
    __syncthreads();

    if (tid < 33) {
        const int p = tid;
        const float v = in3[p];
        s33[p] = (p >= 16) ? __fadd_rn(o3[(p >> 4) - 1], v) : v;
    }
    __syncthreads();

    for (int m = tid; m < 513; m += 256) {
        const float v = in2[m];
        s513[m] = (m >= 16) ? __fadd_rn(s33[(m >> 4) - 1], v) : v;
    }
    __syncthreads();

    // S[t] = rn(cs_scan(t+15) - cs_scan(t-1)),  cs_scan(-1) = 0
    float* srow = g_Sct + (size_t)c * TN;
    for (int t = tid; t < TN; t += 256) {
        const int i1 = t + 15;
        float hi = (i1 >= 16) ? __fadd_rn(s513[(i1 >> 4) - 1], xs[i1]) : xs[i1];
        float lo = 0.0f;
        if (t > 0) {
            const int i0 = t - 1;
            lo = (i0 >= 16) ? __fadd_rn(s513[(i0 >> 4) - 1], xs[i0]) : xs[i0];
        }
        srow[t] = __fadd_rn(hi, -lo);
    }
}

// ---------------------------------------------------------------------------
// K2: kurtosis. FP ops FROZEN (m2 fused, m4 fully-rounded chain + unfused
// accumulate, true divides). Restructured: no v[17] array (two-pass direct
// smem reads — tiny live register set, no spills); results kept in kk[8] and
// written as two float4 to the [c][t] layout for vectorized scan loads.
// ---------------------------------------------------------------------------
__global__ void __launch_bounds__(512) k_kurt() {
    const int t0  = blockIdx.x * 8;
    const int tid = threadIdx.x;            // 512
    __shared__ float sh[8][C + 17];

#pragma unroll
    for (int r = 0; r < 8; r++) {
        int e  = r * 512 + tid;
        int cc = e >> 3, tt = e & 7;
        sh[tt][cc + 8] = g_Sct[(size_t)cc * TN + t0 + tt];
    }
    if (tid < 64) {
        int tt = tid >> 3, j = tid & 7;
        sh[tt][j]         = 0.0f;
        sh[tt][C + 8 + j] = 0.0f;
    }
    __syncthreads();

    const int c = tid;
    float kk[8];
#pragma unroll
    for (int tt = 0; tt < 8; tt++) {
        const float* vp = &sh[tt][c];

        float s = 0.0f;
#pragma unroll
        for (int i = 0; i < 17; i++) s = __fadd_rn(s, vp[i]);
        float mu = __fdiv_rn(s, 17.0f);

        float m2 = 0.0f, m4 = 0.0f;
#pragma unroll
        for (int i = 0; i < 17; i++) {
            float d  = __fadd_rn(vp[i], -mu);
            m2 = __fmaf_rn(d, d, m2);            // fused accumulate
            float d2 = __fmul_rn(d, d);
            float d3 = __fmul_rn(d2, d);
            float d4 = __fmul_rn(d3, d);
            m4 = __fadd_rn(m4, d4);              // unfused accumulate
        }
        m2 = __fdiv_rn(m2, 17.0f);
        m4 = __fdiv_rn(m4, 17.0f);
        kk[tt] = __fadd_rn(__fdiv_rn(m4, __fmul_rn(m2, m2)), -3.0f);
    }

    float* krow = g_Kct + (size_t)c * TN + t0;   // 32B-aligned (t0 mult of 8)
    *(float4*)(krow)     = make_float4(kk[0], kk[1], kk[2], kk[3]);
    *(float4*)(krow + 4) = make_float4(kk[4], kk[5], kk[6], kk[7]);
}

// ---------------------------------------------------------------------------
// K3: serial LIF scan, one thread per channel. FP ops FROZEN; structural:
//  - carried chain FFMA -> FSETP(mem1>1) -> FSEL = 12 cyc/step
//    ((mem1>1) <=> (d>0): Sterbenz-exact in [0.5,2], sign preserved outside)
//  - ping-pong 16-deep buffers, float4 loads (g_Kct [c][t] now t-minor) and
//    float4 spike stores: ~1 mem-issue-cyc/step instead of ~12.
// ---------------------------------------------------------------------------
__global__ void __launch_bounds__(32) k_scan(const float* __restrict__ inp,
                                             const float* __restrict__ w_init,
                                             float* __restrict__ out) {
    const int c = blockIdx.x * 32 + threadIdx.x;
    const float* xrow = inp + (size_t)c * T;
    const float* krow = g_Kct + (size_t)c * TN;
    float*       orow = out + (size_t)c * T;

    float w   = w_init[c];
    float mem = 0.0f;

    float ka[16], xa[16], kb[16], xb[16];

    // chunk 0 (t = 0..15): left x-padding
#pragma unroll
    for (int q = 0; q < 4; q++)
        *(float4*)&ka[q * 4] = *(const float4*)(krow + q * 4);
#pragma unroll
    for (int u = 0; u < 16; u++)
        xa[u] = (u >= PAD) ? xrow[u - PAD] : 0.0f;

#define LOADB(tb)                                                          \
    do {                                                                   \
        _Pragma("unroll")                                                  \
        for (int q = 0; q < 4; q++) {                                      \
            *(float4*)&kb[q * 4] = *(const float4*)(krow + (tb) + q * 4);  \
            *(float4*)&xb[q * 4] = *(const float4*)(xrow + (tb) - PAD + q * 4); \
        }                                                                  \
    } while (0)
#define LOADA(tb)                                                          \
    do {                                                                   \
        _Pragma("unroll")                                                  \
        for (int q = 0; q < 4; q++) {                                      \
            *(float4*)&ka[q * 4] = *(const float4*)(krow + (tb) + q * 4);  \
            *(float4*)&xa[q * 4] = *(const float4*)(xrow + (tb) - PAD + q * 4); \
        }                                                                  \
    } while (0)
#define STEP(kv, xv)                                                       \
    {                                                                      \
        float hk = __fmul_rn(0.5f, (kv));                                  \
        w = __fmaf_rn(0.5f, w, hk);                                        \
        w = fmaxf(w, 0.0f);                                                \
        w = fminf(w, 10.0f);                                               \
        float wx   = __fmul_rn(w, (xv));                                   \
        float mem1 = __fmaf_rn(0.95f, mem, wx);                            \
        float d    = __fadd_rn(mem1, -1.0f);                               \
        bool  p    = (mem1 > 1.0f);                                        \
        sp[u] = p ? 1.0f : 0.0f;                                           \
        mem = p ? d : mem1;                                                \
    }
#define PROCESS(kbuf, xbuf, base)                                          \
    do {                                                                   \
        float sp[16];                                                      \
        _Pragma("unroll")                                                  \
        for (int u = 0; u < 16; u++) STEP(kbuf[u], xbuf[u]);               \
        _Pragma("unroll")                                                  \
        for (int q = 0; q < 4; q++)                                        \
            *(float4*)(orow + (base) + q * 4) = *(float4*)&sp[q * 4];      \
    } while (0)

    for (int blk = 0; blk < 255; blk++) {
        const int base = blk * 32;
        LOADB(base + 16);
        PROCESS(ka, xa, base);
        LOADA(base + 32);
        PROCESS(kb, xb, base + 16);
    }
    PROCESS(ka, xa, 8160);          // final chunk (t = 8160..8175)

#undef LOADB
#undef LOADA
#undef STEP
#undef PROCESS

    // tail: out[:, TN:] = inp[:, TN:]  (16 floats, 64B-aligned)
#pragma unroll
    for (int q = 0; q < 4; q++)
        *(float4*)(orow + TN + q * 4) = *(const float4*)(xrow + TN + q * 4);
}

// ---------------------------------------------------------------------------
extern "C" void kernel_launch(void* const* d_in, const int* in_sizes, int n_in,
                              void* d_out, int out_size) {
    const float* inp    = (const float*)d_in[0];   // (512, 8192) f32
    const float* w_init = (const float*)d_in[1];   // (512,)      f32
    float*       out    = (float*)d_out;           // (512, 8192) f32

    k_cumsum<<<C, 256>>>(inp);
    k_kurt  <<<TN / 8, 512>>>();
    k_scan  <<<C / 32, 32>>>(inp, w_init, out);
}